// round 2
// baseline (speedup 1.0000x reference)
#include <cuda_runtime.h>

#define NBATCH  8
#define NCLASS  80
#define NBOX    32
#define NCH     (NBATCH * NCLASS)   // 640
#define THREADS 256

// Partial-sum scratch: per (b,c) channel, 6 deterministic slots:
// slots 0..3 = the 4 chunks of level0 (128x128), slot 4 = level1 (64x64), slot 5 = level2 (32x32).
// Every slot is written every launch -> no zeroing kernel needed, fully deterministic.
__device__ float g_pos[NCH][6];
__device__ float g_neg[NCH][6];
__device__ int   g_np [NCH][6];

__global__ __launch_bounds__(THREADS) void hough_main(
    const float* __restrict__ h0, const float* __restrict__ h1, const float* __restrict__ h2,
    const float* __restrict__ boxes, const int* __restrict__ labels)
{
    int blk = blockIdx.x;
    const float* heat; int chan, slot, W, logW, base, npix;
    if (blk < 2560)      { heat = h0; chan = blk >> 2; int ck = blk & 3; slot = ck;
                           W = 128; logW = 7; base = ck * 4096; npix = 4096; }
    else if (blk < 3200) { heat = h1; chan = blk - 2560; slot = 4;
                           W = 64;  logW = 6; base = 0;         npix = 4096; }
    else                 { heat = h2; chan = blk - 3200; slot = 5;
                           W = 32;  logW = 5; base = 0;         npix = 1024; }
    int b = chan / NCLASS;
    int c = chan - b * NCLASS;

    // ---- gather the boxes of batch b whose label == c (order-independent: used only via max) ----
    __shared__ int   s_cnt;
    __shared__ int   s_x[NBOX], s_y[NBOX], s_r[NBOX];
    __shared__ float s_inv[NBOX];
    if (threadIdx.x == 0) s_cnt = 0;
    __syncthreads();
    if (threadIdx.x < NBOX) {
        int lab = labels[b * NBOX + threadIdx.x];
        if (lab == c) {
            const float* bp = boxes + (size_t)(b * NBOX + threadIdx.x) * 4;
            float Wf = (float)W;
            int x = (int)floorf(bp[0] * Wf);          // floor(cx*W), matches jnp.floor in f32
            int y = (int)floorf(bp[1] * Wf);          // H == W per level
            float s2 = bp[2] * Wf + bp[3] * Wf;       // bw + bh in f32
            int r = (int)floorf(s2 * 0.25f);          // /4.0 exact as *0.25f
            if (r < 1) r = 1;
            float sigma = (float)(2 * r + 1) * (1.0f / 6.0f);
            int k = atomicAdd(&s_cnt, 1);
            s_x[k] = x; s_y[k] = y; s_r[k] = r;
            s_inv[k] = 1.0f / (2.0f * sigma * sigma);
        }
    }
    __syncthreads();
    int nb = s_cnt;

    // ---- fused focal loss over this block's pixel chunk ----
    const float4* hp = (const float4*)(heat + (size_t)chan * (W * W) + base);
    int nvec = npix >> 2;
    float pacc = 0.f, nacc = 0.f; int npos = 0;

    for (int f = threadIdx.x; f < nvec; f += THREADS) {
        float4 v = hp[f];
        int pi0 = base + (f << 2);
        float hv[4] = {v.x, v.y, v.z, v.w};
        #pragma unroll
        for (int e = 0; e < 4; e++) {
            int pi = pi0 + e;
            int y = pi >> logW;
            int x = pi & (W - 1);

            // target = max over matching boxes of windowed gaussian (on-the-fly scatter-max)
            float t = 0.f;
            for (int k = 0; k < nb; k++) {
                int dx = x - s_x[k], dy = y - s_y[k], r = s_r[k];
                if (dx * dx <= r * r && dy * dy <= r * r) {   // |dx|<=r && |dy|<=r
                    float d2 = (float)(dx * dx + dy * dy);
                    t = fmaxf(t, __expf(-d2 * s_inv[k]));     // expf(-0.0)=1.0 exactly at center
                }
            }

            float h = hv[e];
            float p = __fdividef(1.0f, 1.0f + __expf(-h));    // sigmoid
            p = fminf(fmaxf(p, 1e-4f), 1.0f - 1e-4f);         // clip
            if (t == 1.0f) {
                float omp = 1.0f - p;
                pacc += __logf(p) * omp * omp;                // log(p)*(1-p)^2
                npos++;
            } else {
                float omt = 1.0f - t;
                float w = omt * omt; w *= w;                  // (1-t)^4
                nacc += __logf(1.0f - p) * (p * p) * w;       // log(1-p)*p^2*(1-t)^4
            }
        }
    }

    // ---- deterministic block reduction ----
    #pragma unroll
    for (int o = 16; o > 0; o >>= 1) {
        pacc += __shfl_down_sync(0xffffffffu, pacc, o);
        nacc += __shfl_down_sync(0xffffffffu, nacc, o);
        npos += __shfl_down_sync(0xffffffffu, npos, o);
    }
    __shared__ float sp[8], sn[8];
    __shared__ int   si[8];
    int wid = threadIdx.x >> 5, lane = threadIdx.x & 31;
    if (lane == 0) { sp[wid] = pacc; sn[wid] = nacc; si[wid] = npos; }
    __syncthreads();
    if (threadIdx.x == 0) {
        float P = 0.f, Ng = 0.f; int I = 0;
        #pragma unroll
        for (int i = 0; i < 8; i++) { P += sp[i]; Ng += sn[i]; I += si[i]; }
        g_pos[chan][slot] = P; g_neg[chan][slot] = Ng; g_np[chan][slot] = I;
    }
}

__global__ __launch_bounds__(THREADS) void hough_final(float* __restrict__ out)
{
    float acc = 0.f;
    for (int ch = threadIdx.x; ch < NCH; ch += THREADS) {
        float pl = 0.f, nl = 0.f; int np = 0;
        #pragma unroll
        for (int s = 0; s < 6; s++) { pl += g_pos[ch][s]; nl += g_neg[ch][s]; np += g_np[ch][s]; }
        float loss = (np == 0) ? (-nl) : (-(pl + nl) / (float)np);
        acc += fminf(loss, 10.0f);
    }
    #pragma unroll
    for (int o = 16; o > 0; o >>= 1) acc += __shfl_down_sync(0xffffffffu, acc, o);
    __shared__ float sa[8];
    int wid = threadIdx.x >> 5, lane = threadIdx.x & 31;
    if (lane == 0) sa[wid] = acc;
    __syncthreads();
    if (threadIdx.x == 0) {
        float tot = 0.f;
        #pragma unroll
        for (int i = 0; i < 8; i++) tot += sa[i];
        float mean = tot * (1.0f / (float)NCH);
        float lm = log1pf(mean);
        out[0] = lm / (1.0f + lm);
    }
}

extern "C" void kernel_launch(void* const* d_in, const int* in_sizes, int n_in,
                              void* d_out, int out_size)
{
    const float* h0     = (const float*)d_in[0];   // [8,80,128,128]
    const float* h1     = (const float*)d_in[1];   // [8,80,64,64]
    const float* h2     = (const float*)d_in[2];   // [8,80,32,32]
    const float* boxes  = (const float*)d_in[3];   // [8,32,4]
    const int*   labels = (const int*)d_in[4];     // [8,32]
    // d_in[5] = image_sizes (int64) — mathematically cancels, unused.

    hough_main<<<3840, THREADS>>>(h0, h1, h2, boxes, labels);
    hough_final<<<1, THREADS>>>((float*)d_out);
}